// round 3
// baseline (speedup 1.0000x reference)
#include <cuda_runtime.h>
#include <cuda_bf16.h>
#include <cstdint>

// Constants: B=16, C=128, T=8, BR=16, S=8, SY=64, INPUT_SIZE=16384, C*T*BR=16384
// seg_on    = (count of active synapses among 64) >= 16
// branch_on = (count of on segments among 8) >= 4
// Output    = layer2 branch_on at t==0  -> (16, 128, 16)

__device__ __align__(16) uint16_t g_xbits[16384];   // bit b = x[b][j] != 0
__device__ __align__(16) uint16_t g_seg1[131072];   // layer1 seg_on masks
__device__ __align__(16) uint16_t g_act1[16384];    // layer1 branch_on masks

__device__ __forceinline__ uint32_t maj3(uint32_t a, uint32_t b, uint32_t c) {
    return (a & b) | (a & c) | (b & c);
}

// Count 64 one-bit values (16 batch lanes in parallel), return 16-bit mask of
// lanes with count >= 16. sx[0] = 0 (idx==-1), sx[j+1] = batch mask of pos j.
__device__ __forceinline__ uint32_t seg_mask_ge16(const int* __restrict__ p,
                                                  const uint16_t* __restrict__ sx) {
    uint32_t a0 = 0, a1 = 0, a2 = 0, a3 = 0, a4 = 0, a5 = 0, a6 = 0;
    const int4* q = reinterpret_cast<const int4*>(p);
#pragma unroll
    for (int ch = 0; ch < 8; ch++) {
        int4 u = q[2 * ch];
        int4 v = q[2 * ch + 1];
        uint32_t m0 = sx[u.x + 1], m1 = sx[u.y + 1], m2 = sx[u.z + 1], m3 = sx[u.w + 1];
        uint32_t m4 = sx[v.x + 1], m5 = sx[v.y + 1], m6 = sx[v.z + 1], m7 = sx[v.w + 1];

        uint32_t s1 = m0 ^ m1 ^ m2, c1 = maj3(m0, m1, m2);
        uint32_t s2 = m3 ^ m4 ^ m5, c2 = maj3(m3, m4, m5);
        uint32_t s3 = s1 ^ s2 ^ m6, c3 = maj3(s1, s2, m6);
        uint32_t w1 = s3 ^ m7,      c4 = s3 & m7;
        uint32_t s4 = c1 ^ c2 ^ c3, c5 = maj3(c1, c2, c3);
        uint32_t w2 = s4 ^ c4,      c6 = s4 & c4;
        uint32_t w4 = c5 ^ c6,      w8 = c5 & c6;

        uint32_t k, t;
        k = a0 & w1; a0 ^= w1;
        t = a1; a1 = t ^ w2 ^ k; k = maj3(t, w2, k);
        t = a2; a2 = t ^ w4 ^ k; k = maj3(t, w4, k);
        t = a3; a3 = t ^ w8 ^ k; k = maj3(t, w8, k);
        t = a4; a4 = t ^ k;      k = t & k;
        t = a5; a5 = t ^ k;      k = t & k;
        a6 |= k;
    }
    return a4 | a5 | a6;   // count >= 16
}

// >=4 of 8 one-bit values, per bit lane
__device__ __forceinline__ uint32_t branch_ge4(const uint32_t* s) {
    uint32_t o01 = s[0] ^ s[1], t01 = s[0] & s[1];
    uint32_t o23 = s[2] ^ s[3], t23 = s[2] & s[3];
    uint32_t o45 = s[4] ^ s[5], t45 = s[4] & s[5];
    uint32_t o67 = s[6] ^ s[7], t67 = s[6] & s[7];
    uint32_t ca  = o01 & o23;
    uint32_t o03 = o01 ^ o23;
    uint32_t t03 = t01 ^ t23 ^ ca;
    uint32_t f03 = maj3(t01, t23, ca);
    uint32_t cb  = o45 & o67;
    uint32_t o47 = o45 ^ o67;
    uint32_t t47 = t45 ^ t67 ^ cb;
    uint32_t f47 = maj3(t45, t67, cb);
    uint32_t c1 = o03 & o47;
    uint32_t c2 = maj3(t03, t47, c1);
    return f03 | f47 | c2;
}

__device__ __forceinline__ void fill_table(uint16_t* sx, const uint16_t* gtab) {
    if (threadIdx.x == 0) sx[0] = 0;
    const uint32_t* src = reinterpret_cast<const uint32_t*>(gtab);
    for (int i = threadIdx.x; i < 8192; i += 256) {
        uint32_t v = src[i];
        sx[1 + 2 * i] = (uint16_t)(v & 0xFFFFu);
        sx[2 + 2 * i] = (uint16_t)(v >> 16);
    }
    __syncthreads();
}

__global__ void __launch_bounds__(256) k_pack(const float* __restrict__ x) {
    int j = blockIdx.x * 256 + threadIdx.x;
    uint32_t m = 0;
#pragma unroll
    for (int b = 0; b < 16; b++)
        m |= (x[b * 16384 + j] != 0.0f) ? (1u << b) : 0u;
    g_xbits[j] = (uint16_t)m;
}

__global__ void __launch_bounds__(256) k_l1seg(const int* __restrict__ idx) {
    __shared__ uint16_t sx[16386];
    fill_table(sx, g_xbits);
    int sgid = blockIdx.x * 256 + threadIdx.x;      // = branch*8 + seg
    g_seg1[sgid] = (uint16_t)seg_mask_ge16(idx + sgid * 64, sx);
}

__global__ void __launch_bounds__(256) k_l1br() {
    int b = blockIdx.x * 256 + threadIdx.x;
    uint4 v = reinterpret_cast<const uint4*>(g_seg1)[b];
    uint32_t s[8];
    s[0] = v.x & 0xFFFFu; s[1] = v.x >> 16;
    s[2] = v.y & 0xFFFFu; s[3] = v.y >> 16;
    s[4] = v.z & 0xFFFFu; s[5] = v.z >> 16;
    s[6] = v.w & 0xFFFFu; s[7] = v.w >> 16;
    g_act1[b] = (uint16_t)branch_ge4(s);
}

// Layer 2 (t == 0 only): 2048 branches * 8 segments, fused reduce.
// OUTPUT WRITTEN AS FLOAT32 (dtype-mismatch hypothesis test).
__global__ void __launch_bounds__(256) k_l2(const int* __restrict__ idx,
                                            float* __restrict__ out) {
    __shared__ uint16_t sx[16386];
    __shared__ uint32_t segf[256];
    fill_table(sx, g_act1);

    int t = threadIdx.x;
    int sgid = blockIdx.x * 256 + t;                // 0..16383
    int pr  = sgid >> 3;                            // branch = c*16 + br
    int c   = pr >> 4, br = pr & 15, seg = sgid & 7;
    const int* p = idx + (c * 1024 + br * 8 + seg) * 64;
    segf[t] = seg_mask_ge16(p, sx);
    __syncthreads();

    if (t < 32) {
        uint32_t s[8];
#pragma unroll
        for (int i = 0; i < 8; i++) s[i] = segf[t * 8 + i];
        uint32_t ge4 = branch_ge4(s);
        int prl = blockIdx.x * 32 + t;
        int c2 = prl >> 4, br2 = prl & 15;
#pragma unroll
        for (int b = 0; b < 16; b++)
            out[(b * 128 + c2) * 16 + br2] = ((ge4 >> b) & 1u) ? 1.0f : 0.0f;
    }
}

extern "C" void kernel_launch(void* const* d_in, const int* in_sizes, int n_in,
                              void* d_out, int out_size) {
    const float* x = nullptr;
    const int* idxA = nullptr;
    const int* idxB = nullptr;
    for (int i = 0; i < n_in; i++) {
        if (in_sizes[i] == 262144 && !x) {
            x = (const float*)d_in[i];
        } else if (!idxA) {
            idxA = (const int*)d_in[i];
        } else if (!idxB) {
            idxB = (const int*)d_in[i];
        }
    }
    if (!x) { x = (const float*)d_in[0]; idxA = (const int*)d_in[1]; idxB = (const int*)d_in[2]; }

    float* out = (float*)d_out;   // (16, 128, 16), written as float32

    k_pack <<<64, 256>>>(x);
    k_l1seg<<<512, 256>>>(idxA);
    k_l1br <<<64, 256>>>();
    k_l2   <<<64, 256>>>(idxB, out);
}

// round 4
// speedup vs baseline: 1.2655x; 1.2655x over previous
#include <cuda_runtime.h>
#include <cuda_bf16.h>
#include <cstdint>

// Constants: B=16, C=128, T=8, BR=16, S=8, SY=64, INPUT_SIZE=16384, C*T*BR=16384
// seg_on    = (count of active synapses among 64) >= 16
// branch_on = (count of on segments among 8) >= 4
// Output    = layer2 branch_on at t==0 -> (16, 128, 16) float32

__device__ __align__(16) uint16_t g_xbits[16384];   // bit b = x[b][j] != 0
__device__ __align__(16) uint16_t g_act1[16384];    // layer1 branch_on masks

__device__ __forceinline__ uint32_t maj3(uint32_t a, uint32_t b, uint32_t c) {
    return (a & b) | (a & c) | (b & c);
}

#define SHFLX(v, m) __shfl_xor_sync(0xffffffffu, (v), (m))

// 8 lanes (pos = lane&7) cooperatively process one 64-synapse segment:
// each lane gathers its 8 masks, Wallace-8 -> bit-sliced count (0..8),
// then 3 shfl-xor merge levels produce, on every lane of the 8-group,
// the 16-bit batch mask of (segment count >= 16).
__device__ __forceinline__ uint32_t seg_ge16_warp(const int4* __restrict__ p,
                                                  const uint16_t* __restrict__ sx) {
    int4 a = p[0];
    int4 b = p[1];
    uint32_t m0 = sx[a.x + 1], m1 = sx[a.y + 1], m2 = sx[a.z + 1], m3 = sx[a.w + 1];
    uint32_t m4 = sx[b.x + 1], m5 = sx[b.y + 1], m6 = sx[b.z + 1], m7 = sx[b.w + 1];

    // Wallace-8: sum(m0..m7) = w1 + 2*w2 + 4*w4 + 8*w8 per bit lane
    uint32_t s1 = m0 ^ m1 ^ m2, c1 = maj3(m0, m1, m2);
    uint32_t s2 = m3 ^ m4 ^ m5, c2 = maj3(m3, m4, m5);
    uint32_t s3 = s1 ^ s2 ^ m6, c3 = maj3(s1, s2, m6);
    uint32_t w1 = s3 ^ m7,      c4 = s3 & m7;
    uint32_t s4 = c1 ^ c2 ^ c3, c5 = maj3(c1, c2, c3);
    uint32_t w2 = s4 ^ c4,      c6 = s4 & c4;
    uint32_t w4 = c5 ^ c6,      w8 = c5 & c6;

    // level 1 (xor 1): two counts <=8 -> <=16, slices t0..t4
    uint32_t r0 = SHFLX(w1, 1), r1 = SHFLX(w2, 1), r2 = SHFLX(w4, 1), r3 = SHFLX(w8, 1);
    uint32_t k  = w1 & r0;
    uint32_t t0 = w1 ^ r0;
    uint32_t t1 = w2 ^ r1 ^ k;  k = maj3(w2, r1, k);
    uint32_t t2 = w4 ^ r2 ^ k;  k = maj3(w4, r2, k);
    uint32_t t3 = w8 ^ r3 ^ k;
    uint32_t t4 = maj3(w8, r3, k);

    // level 2 (xor 2): two counts <=16 -> <=32, slices u0..u5
    r0 = SHFLX(t0, 2); r1 = SHFLX(t1, 2); r2 = SHFLX(t2, 2); r3 = SHFLX(t3, 2);
    uint32_t r4 = SHFLX(t4, 2);
    k = t0 & r0;
    uint32_t u0 = t0 ^ r0;
    uint32_t u1 = t1 ^ r1 ^ k;  k = maj3(t1, r1, k);
    uint32_t u2 = t2 ^ r2 ^ k;  k = maj3(t2, r2, k);
    uint32_t u3 = t3 ^ r3 ^ k;  k = maj3(t3, r3, k);
    uint32_t u4 = t4 ^ r4 ^ k;
    uint32_t u5 = maj3(t4, r4, k);

    // level 3 (xor 4): sum of two counts <=32; need only (sum >= 16):
    // bit4-or-higher of the sum is set iff u4|v4|u5|v5 or carry into bit 4.
    r0 = SHFLX(u0, 4); r1 = SHFLX(u1, 4); r2 = SHFLX(u2, 4); r3 = SHFLX(u3, 4);
    r4 = SHFLX(u4, 4); uint32_t r5 = SHFLX(u5, 4);
    k = u0 & r0;
    k = maj3(u1, r1, k);
    k = maj3(u2, r2, k);
    k = maj3(u3, r3, k);           // carry into bit 4
    return u4 | r4 | k | u5 | r5;
}

// >=4 of 8 one-bit values, per bit lane
__device__ __forceinline__ uint32_t branch_ge4(const uint32_t* s) {
    uint32_t o01 = s[0] ^ s[1], t01 = s[0] & s[1];
    uint32_t o23 = s[2] ^ s[3], t23 = s[2] & s[3];
    uint32_t o45 = s[4] ^ s[5], t45 = s[4] & s[5];
    uint32_t o67 = s[6] ^ s[7], t67 = s[6] & s[7];
    uint32_t ca  = o01 & o23;
    uint32_t o03 = o01 ^ o23;
    uint32_t t03 = t01 ^ t23 ^ ca;
    uint32_t f03 = maj3(t01, t23, ca);
    uint32_t cb  = o45 & o67;
    uint32_t o47 = o45 ^ o67;
    uint32_t t47 = t45 ^ t67 ^ cb;
    uint32_t f47 = maj3(t45, t67, cb);
    uint32_t c1 = o03 & o47;
    uint32_t c2 = maj3(t03, t47, c1);
    return f03 | f47 | c2;
}

__device__ __forceinline__ void fill_table(uint16_t* sx, const uint16_t* gtab) {
    if (threadIdx.x == 0) sx[0] = 0;
    const uint32_t* src = reinterpret_cast<const uint32_t*>(gtab);
    for (int i = threadIdx.x; i < 8192; i += 256) {
        uint32_t v = src[i];
        sx[1 + 2 * i] = (uint16_t)(v & 0xFFFFu);
        sx[2 + 2 * i] = (uint16_t)(v >> 16);
    }
    __syncthreads();
}

// Pack x (16 x 16384 floats of {0,1}) into per-position 16-bit batch masks.
__global__ void __launch_bounds__(256) k_pack(const float* __restrict__ x) {
    int j = blockIdx.x * 256 + threadIdx.x;
    uint32_t m = 0;
#pragma unroll
    for (int b = 0; b < 16; b++)
        m |= (x[b * 16384 + j] != 0.0f) ? (1u << b) : 0u;
    g_xbits[j] = (uint16_t)m;
}

// Layer 1 fused: block = 8 warps, each warp covers 4 branches (8 iterations
// of 4 segments, 8 lanes per segment, fully coalesced 1KB loads per warp).
__global__ void __launch_bounds__(256) k_layer1(const int* __restrict__ idx) {
    __shared__ uint16_t sx[16386];
    __shared__ uint32_t segbuf[8][32];
    fill_table(sx, g_xbits);

    int w = threadIdx.x >> 5, lane = threadIdx.x & 31;
    int pos = lane & 7, sg = lane >> 3;
    int bb = blockIdx.x * 32 + w * 4;
#pragma unroll
    for (int kk = 0; kk < 8; kk++) {
        int branch = bb + (kk >> 1);
        int seg = ((kk & 1) << 2) + sg;
        const int4* p = reinterpret_cast<const int4*>(
            idx + branch * 512 + seg * 64 + pos * 8);
        uint32_t g = seg_ge16_warp(p, sx);
        if (pos == 0) segbuf[w][(kk >> 1) * 8 + seg] = g;
    }
    __syncwarp();
    if (lane < 4) {
        uint32_t ge4 = branch_ge4(&segbuf[w][lane * 8]);
        g_act1[blockIdx.x * 32 + w * 4 + lane] = (uint16_t)ge4;
    }
}

// Layer 2 (t == 0 only): 2048 (c,br) branches. Block covers 16 branches
// (warp covers 2 branches over 4 iterations). Grid = 128.
__global__ void __launch_bounds__(256) k_layer2(const int* __restrict__ idx,
                                                float* __restrict__ out) {
    __shared__ uint16_t sx[16386];
    __shared__ uint32_t segbuf[8][16];
    fill_table(sx, g_act1);

    int w = threadIdx.x >> 5, lane = threadIdx.x & 31;
    int pos = lane & 7, sg = lane >> 3;
    int pb = blockIdx.x * 16 + w * 2;
#pragma unroll
    for (int kk = 0; kk < 4; kk++) {
        int pr = pb + (kk >> 1);                  // branch = c*16 + br
        int c = pr >> 4, br = pr & 15;
        int seg = ((kk & 1) << 2) + sg;
        // idx2 flat offset of (c, t=0, br, seg, pos*8)
        const int4* p = reinterpret_cast<const int4*>(
            idx + (c * 1024 + br * 8 + seg) * 64 + pos * 8);
        uint32_t g = seg_ge16_warp(p, sx);
        if (pos == 0) segbuf[w][(kk >> 1) * 8 + seg] = g;
    }
    __syncwarp();
    if (lane < 2) {
        uint32_t ge4 = branch_ge4(&segbuf[w][lane * 8]);
        int pr = pb + lane;
        int c = pr >> 4, br = pr & 15;
#pragma unroll
        for (int b = 0; b < 16; b++)
            out[(b * 128 + c) * 16 + br] = ((ge4 >> b) & 1u) ? 1.0f : 0.0f;
    }
}

extern "C" void kernel_launch(void* const* d_in, const int* in_sizes, int n_in,
                              void* d_out, int out_size) {
    const float* x = nullptr;
    const int* idxA = nullptr;
    const int* idxB = nullptr;
    for (int i = 0; i < n_in; i++) {
        if (in_sizes[i] == 262144 && !x) {
            x = (const float*)d_in[i];
        } else if (!idxA) {
            idxA = (const int*)d_in[i];
        } else if (!idxB) {
            idxB = (const int*)d_in[i];
        }
    }
    if (!x) { x = (const float*)d_in[0]; idxA = (const int*)d_in[1]; idxB = (const int*)d_in[2]; }

    float* out = (float*)d_out;   // (16, 128, 16) float32

    k_pack  <<<64, 256>>>(x);
    k_layer1<<<512, 256>>>(idxA);
    k_layer2<<<128, 256>>>(idxB, out);
}